// round 13
// baseline (speedup 1.0000x reference)
#include <cuda_runtime.h>

// VariantCoeLinear1d: 1D Rusanov FV solver, 128 rows x 2048 pts x 256 steps.
// One CTA per row (128 CTAs, single wave). 512 threads x 4 register points.
//
// R13 = R12 (best: 59.6us) software-pipelined:
//  - STG hoisted off the post-barrier tail: frame s-1 (= current u regs) is
//    streamed at the TOP of iteration s, in the pre-barrier slack region.
//    (Iter 1 re-stores frame 0 with identical bytes; frame 255 after loop.)
//  - polys re-paired as (u0,u3) / (u1,u2): the (un1,un2) pack and its h2 for
//    the NEXT step are computed in the current pre-barrier region, so each
//    iteration's barrier-adjacent path carries only one pack.
// Total arithmetic identical to R12; only scheduling changed.

#define BATCH 128
#define NPTS  2048
#define STEPS 256
#define TPB   512
#define PPT   4   // TPB*PPT == NPTS

typedef unsigned long long u64;

static __device__ __forceinline__ u64 pk(float lo, float hi) {
    u64 r; asm("mov.b64 %0,{%1,%2};" : "=l"(r) : "f"(lo), "f"(hi)); return r;
}
static __device__ __forceinline__ void upk(float& lo, float& hi, u64 v) {
    asm("mov.b64 {%0,%1},%2;" : "=f"(lo), "=f"(hi) : "l"(v));
}
static __device__ __forceinline__ u64 f2fma(u64 a, u64 b, u64 c) {
    u64 d; asm("fma.rn.f32x2 %0,%1,%2,%3;" : "=l"(d) : "l"(a), "l"(b), "l"(c)); return d;
}
static __device__ __forceinline__ u64 f2mul(u64 a, u64 b) {
    u64 d; asm("mul.rn.f32x2 %0,%1,%2;" : "=l"(d) : "l"(a), "l"(b)); return d;
}

// fh = (f_l + f_r) - max(a_l,a_r) * (u_r - u_l)   (0.5 folded into HL)
static __device__ __forceinline__ float iface(float ul, float fl, float al,
                                              float ur, float fr, float ar) {
    float am = fmaxf(al, ar);
    return fmaf(-am, ur - ul, fl + fr);
}

// Horner pack: f and |f'| for two points, 10 f32x2 ops.
#define POLY_PACK(U, FLO, FHI, ALO, AHI)                                   \
    do {                                                                   \
        u64 _u2 = f2mul(U, U);                                             \
        u64 _t  = f2fma(CB6, _u2, CB4);                                    \
        _t      = f2fma(_t, U, CB3);                                       \
        _t      = f2fma(_t, U, CB2);                                       \
        _t      = f2fma(_t, U, CB1);                                       \
        u64 _F  = f2mul(_t, U);                                            \
        u64 _s  = f2fma(CA5, _u2, CA3);                                    \
        _s      = f2fma(_s, U, CA2);                                       \
        _s      = f2fma(_s, U, CA1);                                       \
        _s      = f2fma(_s, U, CA0);                                       \
        u64 _A  = _s & ABSM;                                               \
        upk(FLO, FHI, _F);                                                 \
        upk(ALO, AHI, _A);                                                 \
    } while (0)

__global__ void __launch_bounds__(TPB, 1)
vcl_kernel(const float* __restrict__ init, float* __restrict__ out)
{
    __shared__ float sL[2][TPB];   // thread t's FIRST point
    __shared__ float sR[2][TPB];   // thread t's LAST point

    const int row  = blockIdx.x;
    const int tid  = threadIdx.x;
    const int base = tid * PPT;
    const int tl   = (tid > 0) ? tid - 1 : 0;              // edge dummies:
    const int tr   = (tid < TPB - 1) ? tid + 1 : TPB - 1;  // overwritten by BC
    const bool e0  = (tid == 0);
    const bool e1  = (tid == TPB - 1);
    const float HL = 0.5f * (float)(0.002 / (10.0 / 2048.0));  // 0.5*dt/dx

    const double c = 0.1 / 12.0;   // beta/12
    const u64 CB1 = pk(1.5f, 1.5f);
    const u64 CB2 = pk((float)(0.75 * c),        (float)(0.75 * c));
    const u64 CB3 = pk((float)(-0.5 - 2.0 * c),  (float)(-0.5 - 2.0 * c));
    const u64 CB4 = pk((float)(1.5 * c),         (float)(1.5 * c));
    const u64 CB6 = pk((float)(-0.25 * c),       (float)(-0.25 * c));
    const u64 CA0 = pk(1.5f, 1.5f);
    const u64 CA1 = pk((float)(1.5 * c),         (float)(1.5 * c));
    const u64 CA2 = pk((float)(-1.5 - 6.0 * c),  (float)(-1.5 - 6.0 * c));
    const u64 CA3 = pk((float)(6.0 * c),         (float)(6.0 * c));
    const u64 CA5 = pk((float)(-1.5 * c),        (float)(-1.5 * c));
    const u64 ABSM = 0x7fffffff7fffffffULL;

    float u0, u1, u2, u3;
    {
        const float4* ip = reinterpret_cast<const float4*>(init + (size_t)row * NPTS + base);
        float4 a0 = ip[0];
        u0 = a0.x; u1 = a0.y; u2 = a0.z; u3 = a0.w;
    }
    sL[0][tid] = u0;
    sR[0][tid] = u3;

    // prologue: prime the (u1,u2) pack + h2 for iteration 1
    float f1, f2, a1, a2, h2;
    { u64 U = pk(u1, u2); POLY_PACK(U, f1, f2, a1, a2); }
    h2 = iface(u1, f1, a1, u2, f2, a2);

    // op points at frame 0 position: iteration s stores frame s-1 at its top.
    // (Iteration 1 re-stores frame 0 = init, byte-identical.)
    float4* op = reinterpret_cast<float4*>(out + (size_t)row * NPTS + base);
    const size_t ostride = (size_t)BATCH * NPTS / 4;

    #pragma unroll 2
    for (int s = 1; s < STEPS; ++s) {
        const int b = (s - 1) & 1;   // compile-time 0/1 per unrolled copy

        // ======== pre-barrier ========
        // stream frame s-1 (current state) in the slack region
        __stcs(op, make_float4(u0, u1, u2, u3));
        op += ostride;

        // boundary pack (inputs arrived from previous post-barrier tail)
        float f0, f3, a0, a3;
        { u64 U = pk(u0, u3); POLY_PACK(U, f0, f3, a0, a3); }

        float h1 = iface(u0, f0, a0, u1, f1, a1);
        float h3 = iface(u2, f2, a2, u3, f3, a3);
        float un1 = fmaf(-HL, h2 - h1, u1);
        float un2 = fmaf(-HL, h3 - h2, u2);

        // prime next iteration: pack(un1,un2) + its h2 (pure ILP slack)
        float nf1, nf2, na1, na2;
        { u64 U = pk(un1, un2); POLY_PACK(U, nf1, nf2, na1, na2); }
        float nh2 = iface(un1, nf1, na1, un2, nf2, na2);

        // ======== barrier ========
        __syncthreads();

        float um = sR[b][tl];
        float up = sL[b][tr];

        float fm, fp2, am, ap;
        { u64 U = pk(um, up); POLY_PACK(U, fm, fp2, am, ap); }

        float h0 = iface(um, fm, am, u0, f0, a0);
        float h4 = iface(u3, f3, a3, up, fp2, ap);
        float un0 = fmaf(-HL, h1 - h0, u0);
        float un3 = fmaf(-HL, h4 - h3, u3);

        if (e0) un0 = un1;   // outflow BC
        if (e1) un3 = un2;

        // publish next-step boundaries (other buffer; next barrier fences)
        const int nb = s & 1;
        sL[nb][tid] = un0;
        sR[nb][tid] = un3;

        // rotate pipeline state
        u0 = un0; u1 = un1; u2 = un2; u3 = un3;
        f1 = nf1; f2 = nf2; a1 = na1; a2 = na2; h2 = nh2;
    }

    // epilogue: flush frame 255 (current state)
    __stcs(op, make_float4(u0, u1, u2, u3));
}

extern "C" void kernel_launch(void* const* d_in, const int* in_sizes, int n_in,
                              void* d_out, int out_size) {
    const float* init = (const float*)d_in[0];   // [128, 2048] fp32
    // d_in[1] = stepnum (int32) — fixed at 256 by the problem spec
    float* out = (float*)d_out;                  // [256, 128, 2048] fp32
    vcl_kernel<<<BATCH, TPB>>>(init, out);
}

// round 14
// speedup vs baseline: 1.2448x; 1.2448x over previous
#include <cuda_runtime.h>

// VariantCoeLinear1d: 1D Rusanov FV solver, 128 rows x 2048 pts x 256 steps.
// One CTA per row (128 CTAs, single wave). 512 threads x 4 register points.
//
// R14 = R12 (best: 59.6us) with exactly ONE change: the frame STG.128
// (12-cyc issue + L2-write backpressure) moves from the post-barrier tail
// (where it lengthened barrier-arrival skew between the halo-dependent
// updates and the STS publishes) to the TOP of the iteration, storing state
// s-1 from the already-carried u registers. Frame 255 flushed in an
// epilogue. No new loop-carried registers, no repack movs (the R8/R13
// failure mode). Everything else byte-identical to R12.

#define BATCH 128
#define NPTS  2048
#define STEPS 256
#define TPB   512
#define PPT   4   // TPB*PPT == NPTS

typedef unsigned long long u64;

static __device__ __forceinline__ u64 pk(float lo, float hi) {
    u64 r; asm("mov.b64 %0,{%1,%2};" : "=l"(r) : "f"(lo), "f"(hi)); return r;
}
static __device__ __forceinline__ void upk(float& lo, float& hi, u64 v) {
    asm("mov.b64 {%0,%1},%2;" : "=f"(lo), "=f"(hi) : "l"(v));
}
static __device__ __forceinline__ u64 f2fma(u64 a, u64 b, u64 c) {
    u64 d; asm("fma.rn.f32x2 %0,%1,%2,%3;" : "=l"(d) : "l"(a), "l"(b), "l"(c)); return d;
}
static __device__ __forceinline__ u64 f2mul(u64 a, u64 b) {
    u64 d; asm("mul.rn.f32x2 %0,%1,%2;" : "=l"(d) : "l"(a), "l"(b)); return d;
}

// fh = (f_l + f_r) - max(a_l,a_r) * (u_r - u_l)   (0.5 folded into HL)
static __device__ __forceinline__ float iface(float ul, float fl, float al,
                                              float ur, float fr, float ar) {
    float am = fmaxf(al, ar);
    return fmaf(-am, ur - ul, fl + fr);
}

// Horner pack: f and |f'| for two points, 10 f32x2 ops.
#define POLY_PACK(U, FLO, FHI, ALO, AHI)                                   \
    do {                                                                   \
        u64 _u2 = f2mul(U, U);                                             \
        u64 _t  = f2fma(CB6, _u2, CB4);                                    \
        _t      = f2fma(_t, U, CB3);                                       \
        _t      = f2fma(_t, U, CB2);                                       \
        _t      = f2fma(_t, U, CB1);                                       \
        u64 _F  = f2mul(_t, U);                                            \
        u64 _s  = f2fma(CA5, _u2, CA3);                                    \
        _s      = f2fma(_s, U, CA2);                                       \
        _s      = f2fma(_s, U, CA1);                                       \
        _s      = f2fma(_s, U, CA0);                                       \
        u64 _A  = _s & ABSM;                                               \
        upk(FLO, FHI, _F);                                                 \
        upk(ALO, AHI, _A);                                                 \
    } while (0)

__global__ void __launch_bounds__(TPB, 1)
vcl_kernel(const float* __restrict__ init, float* __restrict__ out)
{
    __shared__ float sL[2][TPB];   // thread t's FIRST point
    __shared__ float sR[2][TPB];   // thread t's LAST point

    const int row  = blockIdx.x;
    const int tid  = threadIdx.x;
    const int base = tid * PPT;
    const int tl   = (tid > 0) ? tid - 1 : 0;              // edge dummies:
    const int tr   = (tid < TPB - 1) ? tid + 1 : TPB - 1;  // overwritten by BC
    const bool e0  = (tid == 0);
    const bool e1  = (tid == TPB - 1);
    const float HL = 0.5f * (float)(0.002 / (10.0 / 2048.0));  // 0.5*dt/dx

    const double c = 0.1 / 12.0;   // beta/12
    const u64 CB1 = pk(1.5f, 1.5f);
    const u64 CB2 = pk((float)(0.75 * c),        (float)(0.75 * c));
    const u64 CB3 = pk((float)(-0.5 - 2.0 * c),  (float)(-0.5 - 2.0 * c));
    const u64 CB4 = pk((float)(1.5 * c),         (float)(1.5 * c));
    const u64 CB6 = pk((float)(-0.25 * c),       (float)(-0.25 * c));
    const u64 CA0 = pk(1.5f, 1.5f);
    const u64 CA1 = pk((float)(1.5 * c),         (float)(1.5 * c));
    const u64 CA2 = pk((float)(-1.5 - 6.0 * c),  (float)(-1.5 - 6.0 * c));
    const u64 CA3 = pk((float)(6.0 * c),         (float)(6.0 * c));
    const u64 CA5 = pk((float)(-1.5 * c),        (float)(-1.5 * c));
    const u64 ABSM = 0x7fffffff7fffffffULL;

    float u0, u1, u2, u3;
    {
        const float4* ip = reinterpret_cast<const float4*>(init + (size_t)row * NPTS + base);
        float4 a0 = ip[0];
        u0 = a0.x; u1 = a0.y; u2 = a0.z; u3 = a0.w;
    }
    sL[0][tid] = u0;
    sR[0][tid] = u3;

    // iteration s stores frame s-1 at its top (state s-1 = current u regs)
    float4* op = reinterpret_cast<float4*>(out + (size_t)row * NPTS + base);
    const size_t ostride = (size_t)BATCH * NPTS / 4;

    #pragma unroll 2
    for (int s = 1; s < STEPS; ++s) {
        const int b = (s - 1) & 1;   // compile-time 0/1 per unrolled copy

        // ---- stream frame s-1 in the pre-barrier fat region ----
        __stcs(op, make_float4(u0, u1, u2, u3));
        op += ostride;

        // ======== pre-barrier: owned polys + interior interfaces/updates ====
        float f0, f1, a0, a1, f2, f3, a2, a3;
        { u64 U = pk(u0, u1); POLY_PACK(U, f0, f1, a0, a1); }
        { u64 U = pk(u2, u3); POLY_PACK(U, f2, f3, a2, a3); }

        float h1 = iface(u0, f0, a0, u1, f1, a1);
        float h2 = iface(u1, f1, a1, u2, f2, a2);
        float h3 = iface(u2, f2, a2, u3, f3, a3);
        float un1 = fmaf(-HL, h2 - h1, u1);
        float un2 = fmaf(-HL, h3 - h2, u2);

        // ======== barrier separates prev-step publishes from halo reads ====
        __syncthreads();

        float um = sR[b][tl];
        float up = sL[b][tr];

        float fm, fp2, am, ap;
        { u64 U = pk(um, up); POLY_PACK(U, fm, fp2, am, ap); }

        float h0 = iface(um, fm, am, u0, f0, a0);
        float h4 = iface(u3, f3, a3, up, fp2, ap);
        float un0 = fmaf(-HL, h1 - h0, u0);
        float un3 = fmaf(-HL, h4 - h3, u3);

        if (e0) un0 = un1;   // outflow BC
        if (e1) un3 = un2;

        // publish next-step boundaries (other buffer; next barrier fences)
        const int nb = s & 1;
        sL[nb][tid] = un0;
        sR[nb][tid] = un3;

        u0 = un0; u1 = un1; u2 = un2; u3 = un3;
    }

    // epilogue: flush frame 255 (final state)
    __stcs(op, make_float4(u0, u1, u2, u3));
}

extern "C" void kernel_launch(void* const* d_in, const int* in_sizes, int n_in,
                              void* d_out, int out_size) {
    const float* init = (const float*)d_in[0];   // [128, 2048] fp32
    // d_in[1] = stepnum (int32) — fixed at 256 by the problem spec
    float* out = (float*)d_out;                  // [256, 128, 2048] fp32
    vcl_kernel<<<BATCH, TPB>>>(init, out);
}